// round 1
// baseline (speedup 1.0000x reference)
#include <cuda_runtime.h>

#define BB 8
#define TT 512
#define SS 512
#define HH 128
#define TTILE 16
#define SCHUNK 64

// scratch (allocation-free rule: __device__ globals)
__device__ float g_WS[BB*TT*HH];
__device__ float g_WH[BB*SS*HH];
__device__ float g_CT[BB*TT*HH];

__device__ __forceinline__ float tanh_fast(float x){
    float y; asm("tanh.approx.f32 %0, %1;" : "=f"(y) : "f"(x)); return y;
}

// ---------------------------------------------------------------------------
// K1: projections. out[i][o] = sum_h in[i][h] * W[o][h]
// grid: (128, 2). y=0 -> WS(query,W_s), y=1 -> WH(enc,W_h). 32 rows / block.
// ---------------------------------------------------------------------------
__global__ __launch_bounds__(256) void k_proj(
    const float* __restrict__ q, const float* __restrict__ enc,
    const float* __restrict__ Ws, const float* __restrict__ Wh)
{
    extern __shared__ float sm[];
    float* Wsm  = sm;              // 128 x 129 (padded)
    float* insm = sm + 128*129;    // 32 x 128
    const float* in; const float* W; float* out;
    if (blockIdx.y == 0) { in = q;   W = Ws; out = g_WS; }
    else                 { in = enc; W = Wh; out = g_WH; }
    int tid = threadIdx.x;
    for (int idx = tid; idx < 128*128; idx += 256) {
        int o = idx >> 7, h = idx & 127;
        Wsm[o*129 + h] = W[idx];
    }
    int i0 = blockIdx.x * 32;
    for (int idx = tid; idx < 32*128; idx += 256)
        insm[idx] = in[i0*128 + idx];
    __syncthreads();

    int o = tid & 127, ih = tid >> 7;   // ih selects 16-row half
    float acc[16];
    #pragma unroll
    for (int k = 0; k < 16; k++) acc[k] = 0.f;
    #pragma unroll 4
    for (int h = 0; h < 128; h++) {
        float w = Wsm[o*129 + h];                    // conflict-free (pad 129)
        #pragma unroll
        for (int k = 0; k < 16; k++)
            acc[k] += w * insm[(ih*16 + k)*128 + h]; // warp-broadcast
    }
    #pragma unroll
    for (int k = 0; k < 16; k++)
        out[(i0 + ih*16 + k)*128 + o] = acc[k];
}

// ---------------------------------------------------------------------------
// K2: fused scores + masked softmax + ct.  grid 256 = (b, t-tile of 16)
// ---------------------------------------------------------------------------
__global__ __launch_bounds__(256, 2) void k_attn(
    const float* __restrict__ enc, const int* __restrict__ lens,
    const float* __restrict__ vvec)
{
    extern __shared__ float sm[];
    float* wssm   = sm;                    // 16 x 128
    float* whT    = wssm + TTILE*128;      // 128 x 65 (transposed, padded); reused as enc chunk 64x128
    float* scores = whT + 128*65;          // 16 x 512
    float* vsm    = scores + TTILE*512;    // 128
    float* invsum = vsm + 128;             // 16

    int tid = threadIdx.x;
    int b  = blockIdx.x >> 5;
    int t0 = (blockIdx.x & 31) * TTILE;
    int len = __ldg(&lens[b]);

    for (int idx = tid; idx < TTILE*128; idx += 256)
        wssm[idx] = g_WS[(b*TT + t0)*128 + idx];
    if (tid < 128) vsm[tid] = vvec[tid];
    __syncthreads();

    int warp = tid >> 5, lane = tid & 31;

    // ---- Phase B: scores. warp task = (t-pair, 32 s). MUFU.TANH bound. ----
    for (int s0 = 0; s0 < SS; s0 += SCHUNK) {
        for (int idx = tid; idx < SCHUNK*128; idx += 256) {
            int s = idx >> 7, h = idx & 127;
            whT[h*65 + s] = g_WH[(b*SS + s0 + s)*128 + h];  // transpose into smem
        }
        __syncthreads();
        #pragma unroll
        for (int it = 0; it < 2; it++) {
            int task = warp + 8*it;           // 16 tasks = 8 t-pairs x 2 s-halves
            int tp = task >> 1, sh = task & 1;
            int tA = tp*2, tB = tA + 1;
            int s = sh*32 + lane;
            float acc0 = 0.f, acc1 = 0.f;
            const float* wsA = wssm + tA*128;
            const float* wsB = wssm + tB*128;
            #pragma unroll 8
            for (int h = 0; h < 128; h++) {
                float wh = whT[h*65 + s];     // conflict-free, 1 load / 2 tanh
                float vv = vsm[h];
                acc0 += vv * tanh_fast(wh + wsA[h]);
                acc1 += vv * tanh_fast(wh + wsB[h]);
            }
            int sg = s0 + s;
            float m = (sg < len) ? 1.f : 0.f; // reference quirk: zero, not -inf
            scores[tA*512 + sg] = acc0 * m;
            scores[tB*512 + sg] = acc1 * m;
        }
        __syncthreads();
    }

    // ---- Phase C: softmax over full 512 (zeros included) ----
    #pragma unroll
    for (int it = 0; it < 2; it++) {
        int t = warp + 8*it;
        float* row = scores + t*512;
        float loc[16];
        float mx = -1e30f;
        #pragma unroll
        for (int k = 0; k < 16; k++) { loc[k] = row[lane + 32*k]; mx = fmaxf(mx, loc[k]); }
        #pragma unroll
        for (int o = 16; o > 0; o >>= 1) mx = fmaxf(mx, __shfl_xor_sync(0xffffffffu, mx, o));
        float sum = 0.f;
        #pragma unroll
        for (int k = 0; k < 16; k++) {
            float p = __expf(loc[k] - mx);
            row[lane + 32*k] = p;
            sum += p;
        }
        #pragma unroll
        for (int o = 16; o > 0; o >>= 1) sum += __shfl_xor_sync(0xffffffffu, sum, o);
        if (lane == 0) invsum[t] = 1.f / sum;
    }

    // ---- Phase D: ct[t,h] = (1/sum) * sum_s p[t,s] * enc[s,h] ----
    int tp = tid >> 5;            // t-pair 0..7
    int h0 = (tid & 31) * 4;      // 4 h per thread
    int tA = tp*2, tB = tA + 1;
    float a0x=0,a0y=0,a0z=0,a0w=0, a1x=0,a1y=0,a1z=0,a1w=0;
    float* encsm = whT;           // reuse (64 x 128, no pad)
    for (int s0 = 0; s0 < SS; s0 += SCHUNK) {
        __syncthreads();          // protect previous chunk reads (also covers softmax writes)
        for (int idx = tid; idx < SCHUNK*128; idx += 256)
            encsm[idx] = enc[(b*SS + s0)*128 + idx];
        __syncthreads();
        #pragma unroll 4
        for (int ss = 0; ss < SCHUNK; ss++) {
            float4 e = *(const float4*)(encsm + ss*128 + h0);
            float p0 = scores[tA*512 + s0 + ss];   // broadcast
            float p1 = scores[tB*512 + s0 + ss];
            a0x += p0*e.x; a0y += p0*e.y; a0z += p0*e.z; a0w += p0*e.w;
            a1x += p1*e.x; a1y += p1*e.y; a1z += p1*e.z; a1w += p1*e.w;
        }
    }
    float i0 = invsum[tA], i1 = invsum[tB];
    float4 r0 = make_float4(a0x*i0, a0y*i0, a0z*i0, a0w*i0);
    float4 r1 = make_float4(a1x*i1, a1y*i1, a1z*i1, a1w*i1);
    *(float4*)(g_CT + (b*TT + t0 + tA)*128 + h0) = r0;
    *(float4*)(g_CT + (b*TT + t0 + tB)*128 + h0) = r1;
}

// ---------------------------------------------------------------------------
// K3: out[t,o] = tanh( sum_c W[o,c]*concat[t,c] + bias[o] ), c in [0,256)
// grid 256 = (b, t-tile of 16); 256 threads = 128 o x 2 k-split
// ---------------------------------------------------------------------------
__global__ __launch_bounds__(256) void k_out(
    const float* __restrict__ q, const float* __restrict__ Wout,
    const float* __restrict__ bias, float* __restrict__ out)
{
    extern __shared__ float sm[];
    float* concat = sm;               // 16 x 256
    float* Wt     = concat + 16*256;  // 64 x 128 (transposed chunk; reused for reduction)
    float* bsm    = Wt + 64*128;      // 128

    int tid = threadIdx.x;
    int b  = blockIdx.x >> 5;
    int t0 = (blockIdx.x & 31) * 16;

    for (int idx = tid; idx < 16*256; idx += 256) {
        int t = idx >> 8, c = idx & 255;
        concat[idx] = (c < 128) ? g_CT[(b*TT + t0 + t)*128 + c]
                                : q   [(b*TT + t0 + t)*128 + (c - 128)];
    }
    if (tid < 128) bsm[tid] = bias[tid];

    int o  = tid & 127, ks = tid >> 7;
    int ol = tid >> 1,  cp = tid & 1;     // loader mapping
    float acc[16];
    #pragma unroll
    for (int k = 0; k < 16; k++) acc[k] = 0.f;

    for (int c0 = 0; c0 < 256; c0 += 64) {
        __syncthreads();
        #pragma unroll
        for (int j = 0; j < 8; j++) {     // each thread: 32 floats of one W row
            float4 w4 = *(const float4*)(Wout + ol*256 + c0 + cp*32 + j*4);
            int cl = cp*32 + j*4;
            Wt[(cl+0)*128 + ol] = w4.x;
            Wt[(cl+1)*128 + ol] = w4.y;
            Wt[(cl+2)*128 + ol] = w4.z;
            Wt[(cl+3)*128 + ol] = w4.w;
        }
        __syncthreads();
        for (int cl = ks*32; cl < ks*32 + 32; cl++) {
            float w = Wt[cl*128 + o];     // conflict-free across lanes
            int c = c0 + cl;
            #pragma unroll
            for (int t = 0; t < 16; t++)
                acc[t] += w * concat[t*256 + c];  // broadcast
        }
    }
    __syncthreads();
    if (ks == 1) {
        #pragma unroll
        for (int t = 0; t < 16; t++) Wt[t*128 + o] = acc[t];
    }
    __syncthreads();
    if (ks == 0) {
        #pragma unroll
        for (int t = 0; t < 16; t++) {
            float r = tanhf(acc[t] + Wt[t*128 + o] + bsm[o]);
            out[(b*TT + t0 + t)*128 + o] = r;
        }
    }
}

// ---------------------------------------------------------------------------
extern "C" void kernel_launch(void* const* d_in, const int* in_sizes, int n_in,
                              void* d_out, int out_size)
{
    (void)in_sizes; (void)n_in; (void)out_size;
    const float* q    = (const float*)d_in[0];
    const float* enc  = (const float*)d_in[1];
    const int*   lens = (const int*)  d_in[2];
    const float* Wh   = (const float*)d_in[3];
    const float* Ws   = (const float*)d_in[4];
    const float* v    = (const float*)d_in[5];
    const float* Wout = (const float*)d_in[6];
    const float* bias = (const float*)d_in[7];
    float* out = (float*)d_out;

    int sm1 = (128*129 + 32*128) * 4;                        // 82432 B
    int sm2 = (TTILE*128 + 128*65 + TTILE*512 + 128 + 16)*4; // 74816 B
    int sm3 = (16*256 + 64*128 + 128) * 4;                   // 49664 B
    cudaFuncSetAttribute(k_proj, cudaFuncAttributeMaxDynamicSharedMemorySize, sm1);
    cudaFuncSetAttribute(k_attn, cudaFuncAttributeMaxDynamicSharedMemorySize, sm2);
    cudaFuncSetAttribute(k_out,  cudaFuncAttributeMaxDynamicSharedMemorySize, sm3);

    dim3 g1(128, 2);
    k_proj<<<g1, 256, sm1>>>(q, enc, Ws, Wh);
    k_attn<<<256, 256, sm2>>>(enc, lens, v);
    k_out <<<256, 256, sm3>>>(q, Wout, bias, out);
}

// round 2
// speedup vs baseline: 1.0774x; 1.0774x over previous
#include <cuda_runtime.h>

#define BB 8
#define TT 512
#define SS 512
#define HH 128
#define TTILE 16
#define SCHUNK 64

// scratch (allocation-free rule: __device__ globals)
__device__ float g_WS[BB*TT*HH];
__device__ float g_WH[BB*SS*HH];
__device__ float g_CT[BB*TT*HH];

__device__ __forceinline__ float tanh_fast(float x){
    float y; asm("tanh.approx.f32 %0, %1;" : "=f"(y) : "f"(x)); return y;
}

// ---------------------------------------------------------------------------
// K1: projections. out[i][o] = sum_h in[i][h] * W[o][h]
// grid (64, 2): y=0 -> WS(query,W_s), y=1 -> WH(enc,W_h). 64 rows / block.
// Thread = 8 rows x 4 cols (cols strided by 32): 12 LDS / 32 FFMA per h.
// ---------------------------------------------------------------------------
__global__ __launch_bounds__(256) void k_proj(
    const float* __restrict__ q, const float* __restrict__ enc,
    const float* __restrict__ Ws, const float* __restrict__ Wh)
{
    extern __shared__ float sm[];
    float* Wsm  = sm;              // 128 x 129 (pad 129: odd stride -> conflict-free)
    float* insm = sm + 128*129;    // 64 x 128
    const float* in; const float* W; float* out;
    if (blockIdx.y == 0) { in = q;   W = Ws; out = g_WS; }
    else                 { in = enc; W = Wh; out = g_WH; }
    int tid = threadIdx.x;
    for (int idx = tid; idx < 128*128; idx += 256) {
        int o = idx >> 7, h = idx & 127;
        Wsm[o*129 + h] = W[idx];
    }
    int i0 = blockIdx.x * 64;
    {
        const float4* inv = (const float4*)(in + i0*128);
        float4* insv = (float4*)insm;
        for (int idx = tid; idx < 64*128/4; idx += 256) insv[idx] = inv[idx];
    }
    __syncthreads();

    int cg = tid & 31;         // lane -> col group; cols = cg + 32*j
    int rg = tid >> 5;         // warp -> row group; rows = rg*8 + r (warp-uniform)
    float acc[8][4];
    #pragma unroll
    for (int r = 0; r < 8; r++)
        #pragma unroll
        for (int j = 0; j < 4; j++) acc[r][j] = 0.f;

    #pragma unroll 4
    for (int h = 0; h < 128; h++) {
        float cv[4];
        #pragma unroll
        for (int j = 0; j < 4; j++) cv[j] = Wsm[(cg + 32*j)*129 + h];  // conflict-free
        float rv[8];
        #pragma unroll
        for (int r = 0; r < 8; r++) rv[r] = insm[(rg*8 + r)*128 + h];  // broadcast
        #pragma unroll
        for (int r = 0; r < 8; r++)
            #pragma unroll
            for (int j = 0; j < 4; j++) acc[r][j] += rv[r]*cv[j];
    }
    #pragma unroll
    for (int r = 0; r < 8; r++)
        #pragma unroll
        for (int j = 0; j < 4; j++)
            out[(i0 + rg*8 + r)*128 + cg + 32*j] = acc[r][j];
}

// ---------------------------------------------------------------------------
// K2: fused scores + masked softmax + ct.  grid 256 = (b, t-tile of 16)
// ---------------------------------------------------------------------------
__global__ __launch_bounds__(256, 2) void k_attn(
    const float* __restrict__ enc, const int* __restrict__ lens,
    const float* __restrict__ vvec)
{
    extern __shared__ float sm[];
    float* wssm   = sm;                    // 16 x 128
    float* whT    = wssm + TTILE*128;      // 128 x 65 (transposed, padded); reused as enc chunk 64x128
    float* scores = whT + 128*65;          // 16 x 512
    float* vsm    = scores + TTILE*512;    // 128
    float* invsum = vsm + 128;             // 16

    int tid = threadIdx.x;
    int b  = blockIdx.x >> 5;
    int t0 = (blockIdx.x & 31) * TTILE;
    int len = __ldg(&lens[b]);

    for (int idx = tid; idx < TTILE*128; idx += 256)
        wssm[idx] = g_WS[(b*TT + t0)*128 + idx];
    if (tid < 128) vsm[tid] = vvec[tid];
    __syncthreads();

    int warp = tid >> 5, lane = tid & 31;

    // ---- Phase B: scores. warp task = (t-quad, 32 s). MUFU.TANH bound. ----
    {
        int tq = warp >> 1, sh = warp & 1;   // 4 t-quads x 2 s-halves = 8 warps
        int s  = sh*32 + lane;
        const float* ws0 = wssm + (tq*4 + 0)*128;
        const float* ws1 = wssm + (tq*4 + 1)*128;
        const float* ws2 = wssm + (tq*4 + 2)*128;
        const float* ws3 = wssm + (tq*4 + 3)*128;
        for (int s0 = 0; s0 < SS; s0 += SCHUNK) {
            for (int idx = tid; idx < SCHUNK*128; idx += 256) {
                int ss = idx >> 7, h = idx & 127;
                whT[h*65 + ss] = g_WH[(b*SS + s0 + ss)*128 + h];  // transpose into smem
            }
            __syncthreads();
            float a0 = 0.f, a1 = 0.f, a2 = 0.f, a3 = 0.f;
            #pragma unroll 8
            for (int h = 0; h < 128; h++) {
                float wh = whT[h*65 + s];     // conflict-free, 1 load / 4 tanh
                float vv = vsm[h];
                a0 += vv * tanh_fast(wh + ws0[h]);
                a1 += vv * tanh_fast(wh + ws1[h]);
                a2 += vv * tanh_fast(wh + ws2[h]);
                a3 += vv * tanh_fast(wh + ws3[h]);
            }
            int sg = s0 + s;
            float m = (sg < len) ? 1.f : 0.f; // reference quirk: zero, not -inf
            scores[(tq*4 + 0)*512 + sg] = a0 * m;
            scores[(tq*4 + 1)*512 + sg] = a1 * m;
            scores[(tq*4 + 2)*512 + sg] = a2 * m;
            scores[(tq*4 + 3)*512 + sg] = a3 * m;
            __syncthreads();
        }
    }

    // ---- Phase C: softmax over full 512 (zeros included) ----
    #pragma unroll
    for (int it = 0; it < 2; it++) {
        int t = warp + 8*it;
        float* row = scores + t*512;
        float loc[16];
        float mx = -1e30f;
        #pragma unroll
        for (int k = 0; k < 16; k++) { loc[k] = row[lane + 32*k]; mx = fmaxf(mx, loc[k]); }
        #pragma unroll
        for (int o = 16; o > 0; o >>= 1) mx = fmaxf(mx, __shfl_xor_sync(0xffffffffu, mx, o));
        float sum = 0.f;
        #pragma unroll
        for (int k = 0; k < 16; k++) {
            float p = __expf(loc[k] - mx);
            row[lane + 32*k] = p;
            sum += p;
        }
        #pragma unroll
        for (int o = 16; o > 0; o >>= 1) sum += __shfl_xor_sync(0xffffffffu, sum, o);
        if (lane == 0) invsum[t] = 1.f / sum;
    }

    // ---- Phase D: ct[t,h] = (1/sum) * sum_s p[t,s] * enc[s,h] ----
    int tp = tid >> 5;            // t-pair 0..7
    int h0 = (tid & 31) * 4;      // 4 h per thread
    int tA = tp*2, tB = tA + 1;
    float a0x=0,a0y=0,a0z=0,a0w=0, a1x=0,a1y=0,a1z=0,a1w=0;
    float* encsm = whT;           // reuse (64 x 128, no pad)
    for (int s0 = 0; s0 < SS; s0 += SCHUNK) {
        __syncthreads();          // protect previous chunk reads (also covers softmax writes)
        for (int idx = tid; idx < SCHUNK*128; idx += 256)
            encsm[idx] = enc[(b*SS + s0)*128 + idx];
        __syncthreads();
        #pragma unroll 4
        for (int ss = 0; ss < SCHUNK; ss++) {
            float4 e = *(const float4*)(encsm + ss*128 + h0);
            float p0 = scores[tA*512 + s0 + ss];   // broadcast
            float p1 = scores[tB*512 + s0 + ss];
            a0x += p0*e.x; a0y += p0*e.y; a0z += p0*e.z; a0w += p0*e.w;
            a1x += p1*e.x; a1y += p1*e.y; a1z += p1*e.z; a1w += p1*e.w;
        }
    }
    float i0 = invsum[tA], i1 = invsum[tB];
    float4 r0 = make_float4(a0x*i0, a0y*i0, a0z*i0, a0w*i0);
    float4 r1 = make_float4(a1x*i1, a1y*i1, a1z*i1, a1w*i1);
    *(float4*)(g_CT + (b*TT + t0 + tA)*128 + h0) = r0;
    *(float4*)(g_CT + (b*TT + t0 + tB)*128 + h0) = r1;
}

// ---------------------------------------------------------------------------
// K3: out[t,o] = tanh( sum_c W[o,c]*concat[t,c] + bias[o] ), c in [0,256)
// grid 256 = (b, t-tile of 16); thread = 4t x 2o (o strided by 64).
// W staged in c-chunks of 128 (pad 129), occ 2.
// ---------------------------------------------------------------------------
__global__ __launch_bounds__(256, 2) void k_out(
    const float* __restrict__ q, const float* __restrict__ Wout,
    const float* __restrict__ bias, float* __restrict__ out)
{
    extern __shared__ float sm[];
    float* concat = sm;               // 16 x 256
    float* Wsm    = concat + 16*256;  // 128 x 129 (c-chunk, pad)
    float* bsm    = Wsm + 128*129;    // 128

    int tid = threadIdx.x;
    int b  = blockIdx.x >> 5;
    int t0 = (blockIdx.x & 31) * 16;

    for (int idx = tid; idx < 16*256; idx += 256) {
        int t = idx >> 8, c = idx & 255;
        concat[idx] = (c < 128) ? g_CT[(b*TT + t0 + t)*128 + c]
                                : q   [(b*TT + t0 + t)*128 + (c - 128)];
    }
    if (tid < 128) bsm[tid] = bias[tid];

    int og = tid & 63;          // o = og, og + 64
    int tg = tid >> 6;          // 4 t-groups x 4 t; warp-uniform
    float acc[4][2];
    #pragma unroll
    for (int k = 0; k < 4; k++) { acc[k][0] = 0.f; acc[k][1] = 0.f; }

    for (int c0 = 0; c0 < 256; c0 += 128) {
        __syncthreads();
        for (int idx = tid; idx < 128*128; idx += 256) {
            int o = idx >> 7, cl = idx & 127;
            Wsm[o*129 + cl] = Wout[o*256 + c0 + cl];
        }
        __syncthreads();
        #pragma unroll 4
        for (int cl = 0; cl < 128; cl++) {
            float w0 = Wsm[og*129 + cl];         // conflict-free (odd stride)
            float w1 = Wsm[(og + 64)*129 + cl];
            int c = c0 + cl;
            #pragma unroll
            for (int k = 0; k < 4; k++) {
                float cc = concat[(tg*4 + k)*256 + c];  // broadcast
                acc[k][0] += w0 * cc;
                acc[k][1] += w1 * cc;
            }
        }
    }
    #pragma unroll
    for (int k = 0; k < 4; k++) {
        int t = t0 + tg*4 + k;
        out[(b*TT + t)*128 + og     ] = tanhf(acc[k][0] + bsm[og]);
        out[(b*TT + t)*128 + og + 64] = tanhf(acc[k][1] + bsm[og + 64]);
    }
}

// ---------------------------------------------------------------------------
extern "C" void kernel_launch(void* const* d_in, const int* in_sizes, int n_in,
                              void* d_out, int out_size)
{
    (void)in_sizes; (void)n_in; (void)out_size;
    const float* q    = (const float*)d_in[0];
    const float* enc  = (const float*)d_in[1];
    const int*   lens = (const int*)  d_in[2];
    const float* Wh   = (const float*)d_in[3];
    const float* Ws   = (const float*)d_in[4];
    const float* v    = (const float*)d_in[5];
    const float* Wout = (const float*)d_in[6];
    const float* bias = (const float*)d_in[7];
    float* out = (float*)d_out;

    int sm1 = (128*129 + 64*128) * 4;                        // 98816 B
    int sm2 = (TTILE*128 + 128*65 + TTILE*512 + 128 + 16)*4; // 74816 B
    int sm3 = (16*256 + 128*129 + 128) * 4;                  // 82944 B
    cudaFuncSetAttribute(k_proj, cudaFuncAttributeMaxDynamicSharedMemorySize, sm1);
    cudaFuncSetAttribute(k_attn, cudaFuncAttributeMaxDynamicSharedMemorySize, sm2);
    cudaFuncSetAttribute(k_out,  cudaFuncAttributeMaxDynamicSharedMemorySize, sm3);

    dim3 g1(64, 2);
    k_proj<<<g1, 256, sm1>>>(q, enc, Ws, Wh);
    k_attn<<<256, 256, sm2>>>(enc, lens, v);
    k_out <<<256, 256, sm3>>>(q, Wout, bias, out);
}

// round 3
// speedup vs baseline: 1.2360x; 1.1472x over previous
#include <cuda_runtime.h>

#define BB 8
#define TT 512
#define SS 512
#define HH 128
#define TTILE 16
#define SCHUNK 64

// scratch (allocation-free rule: __device__ globals)
__device__ float g_WS[BB*TT*HH];
__device__ float g_WH[BB*SS*HH];
__device__ float g_CT[BB*TT*HH];

__device__ __forceinline__ float tanh_fast(float x){
    float y; asm("tanh.approx.f32 %0, %1;" : "=f"(y) : "f"(x)); return y;
}

// ---------------------------------------------------------------------------
// K1: projections. out[i][o] = sum_h in[i][h] * W[o][h]
// grid (128, 2): y=0 -> WS(query,W_s), y=1 -> WH(enc,W_h). 32 rows / block.
// Thread = 4 rows x 4 cols; h vectorized by float4; W staged in 32-h chunks.
// Per 4h: 8 LDS.128 / 64 FFMA.
// ---------------------------------------------------------------------------
__global__ __launch_bounds__(256) void k_proj(
    const float* __restrict__ q, const float* __restrict__ enc,
    const float* __restrict__ Ws, const float* __restrict__ Wh)
{
    extern __shared__ float sm[];
    float* insm = sm;            // 32 x 128
    float* Wsm  = sm + 32*128;   // 128 cols x 36 (stride 36: LDS.128 conflict-free)

    const float* in; const float* W; float* out;
    if (blockIdx.y == 0) { in = q;   W = Ws; out = g_WS; }
    else                 { in = enc; W = Wh; out = g_WH; }
    int tid = threadIdx.x;
    int i0 = blockIdx.x * 32;

    {   // stage input rows (float4, coalesced)
        const float4* inv = (const float4*)(in + i0*128);
        float4* insv = (float4*)insm;
        #pragma unroll
        for (int k = 0; k < 4; k++) insv[tid + 256*k] = inv[tid + 256*k];
    }

    int cg = tid & 31;          // cols = cg + 32*j
    int rg = tid >> 5;          // rows = rg*4 + r (warp-uniform)
    float acc[4][4];
    #pragma unroll
    for (int r = 0; r < 4; r++)
        #pragma unroll
        for (int j = 0; j < 4; j++) acc[r][j] = 0.f;

    #pragma unroll 1
    for (int hc = 0; hc < 4; hc++) {          // 32-h chunks
        __syncthreads();
        #pragma unroll
        for (int k = 0; k < 4; k++) {         // stage W chunk: 1024 float4
            int idx = tid + 256*k;
            int col = idx >> 3, kk = idx & 7;
            float4 w = *(const float4*)(W + col*128 + hc*32 + kk*4);
            *(float4*)(Wsm + col*36 + kk*4) = w;
        }
        __syncthreads();
        #pragma unroll
        for (int k8 = 0; k8 < 8; k8++) {
            float4 cv[4];
            #pragma unroll
            for (int j = 0; j < 4; j++)
                cv[j] = *(const float4*)(Wsm + (cg + 32*j)*36 + k8*4);
            float4 rv[4];
            #pragma unroll
            for (int r = 0; r < 4; r++)
                rv[r] = *(const float4*)(insm + (rg*4 + r)*128 + hc*32 + k8*4);
            #pragma unroll
            for (int r = 0; r < 4; r++)
                #pragma unroll
                for (int j = 0; j < 4; j++) {
                    acc[r][j] += rv[r].x*cv[j].x;
                    acc[r][j] += rv[r].y*cv[j].y;
                    acc[r][j] += rv[r].z*cv[j].z;
                    acc[r][j] += rv[r].w*cv[j].w;
                }
        }
    }
    #pragma unroll
    for (int r = 0; r < 4; r++)
        #pragma unroll
        for (int j = 0; j < 4; j++)
            out[(i0 + rg*4 + r)*128 + cg + 32*j] = acc[r][j];
}

// ---------------------------------------------------------------------------
// K2: fused scores + masked softmax + ct.  grid 256 = (b, t-tile of 16)
// ---------------------------------------------------------------------------
__global__ __launch_bounds__(256, 2) void k_attn(
    const float* __restrict__ enc, const int* __restrict__ lens,
    const float* __restrict__ vvec)
{
    extern __shared__ float sm[];
    float* wssm   = sm;                    // 16 x 128
    float* whT    = wssm + TTILE*128;      // 128 x 65 (transposed, padded); reused as enc chunk 64x128
    float* scores = whT + 128*65;          // 16 x 512
    float* vsm    = scores + TTILE*512;    // 128
    float* invsum = vsm + 128;             // 16

    int tid = threadIdx.x;
    int b  = blockIdx.x >> 5;
    int t0 = (blockIdx.x & 31) * TTILE;
    int len = __ldg(&lens[b]);

    {
        const float4* wsv = (const float4*)(g_WS + (b*TT + t0)*128);
        float4* wssv = (float4*)wssm;
        wssv[tid] = wsv[tid];
        wssv[tid + 256] = wsv[tid + 256];
    }
    if (tid < 128) vsm[tid] = vvec[tid];
    __syncthreads();

    int warp = tid >> 5, lane = tid & 31;

    // ---- Phase B: scores. warp task = (t-quad, 32 s). MUFU.TANH bound. ----
    {
        int tq = warp >> 1, sh = warp & 1;   // 4 t-quads x 2 s-halves = 8 warps
        int s  = sh*32 + lane;
        const float* ws0 = wssm + (tq*4 + 0)*128;
        const float* ws1 = wssm + (tq*4 + 1)*128;
        const float* ws2 = wssm + (tq*4 + 2)*128;
        const float* ws3 = wssm + (tq*4 + 3)*128;
        for (int s0 = 0; s0 < SS; s0 += SCHUNK) {
            for (int idx = tid; idx < SCHUNK*128; idx += 256) {
                int ss = idx >> 7, h = idx & 127;
                whT[h*65 + ss] = g_WH[(b*SS + s0 + ss)*128 + h];  // transpose into smem
            }
            __syncthreads();
            float a0 = 0.f, a1 = 0.f, a2 = 0.f, a3 = 0.f;
            #pragma unroll 4
            for (int h4 = 0; h4 < 32; h4++) {
                int hb = h4*4;
                float4 v4 = *(const float4*)(vsm + hb);
                float4 w0 = *(const float4*)(ws0 + hb);
                float4 w1 = *(const float4*)(ws1 + hb);
                float4 w2 = *(const float4*)(ws2 + hb);
                float4 w3 = *(const float4*)(ws3 + hb);
                float whx = whT[(hb+0)*65 + s];
                float why = whT[(hb+1)*65 + s];
                float whz = whT[(hb+2)*65 + s];
                float whw = whT[(hb+3)*65 + s];
                a0 += v4.x*tanh_fast(whx + w0.x); a0 += v4.y*tanh_fast(why + w0.y);
                a0 += v4.z*tanh_fast(whz + w0.z); a0 += v4.w*tanh_fast(whw + w0.w);
                a1 += v4.x*tanh_fast(whx + w1.x); a1 += v4.y*tanh_fast(why + w1.y);
                a1 += v4.z*tanh_fast(whz + w1.z); a1 += v4.w*tanh_fast(whw + w1.w);
                a2 += v4.x*tanh_fast(whx + w2.x); a2 += v4.y*tanh_fast(why + w2.y);
                a2 += v4.z*tanh_fast(whz + w2.z); a2 += v4.w*tanh_fast(whw + w2.w);
                a3 += v4.x*tanh_fast(whx + w3.x); a3 += v4.y*tanh_fast(why + w3.y);
                a3 += v4.z*tanh_fast(whz + w3.z); a3 += v4.w*tanh_fast(whw + w3.w);
            }
            int sg = s0 + s;
            float m = (sg < len) ? 1.f : 0.f; // reference quirk: zero, not -inf
            scores[(tq*4 + 0)*512 + sg] = a0 * m;
            scores[(tq*4 + 1)*512 + sg] = a1 * m;
            scores[(tq*4 + 2)*512 + sg] = a2 * m;
            scores[(tq*4 + 3)*512 + sg] = a3 * m;
            __syncthreads();
        }
    }

    // ---- Phase C: softmax over full 512 (zeros included) ----
    #pragma unroll
    for (int it = 0; it < 2; it++) {
        int t = warp + 8*it;
        float* row = scores + t*512;
        float loc[16];
        float mx = -1e30f;
        #pragma unroll
        for (int k = 0; k < 16; k++) { loc[k] = row[lane + 32*k]; mx = fmaxf(mx, loc[k]); }
        #pragma unroll
        for (int o = 16; o > 0; o >>= 1) mx = fmaxf(mx, __shfl_xor_sync(0xffffffffu, mx, o));
        float sum = 0.f;
        #pragma unroll
        for (int k = 0; k < 16; k++) {
            float p = __expf(loc[k] - mx);
            row[lane + 32*k] = p;
            sum += p;
        }
        #pragma unroll
        for (int o = 16; o > 0; o >>= 1) sum += __shfl_xor_sync(0xffffffffu, sum, o);
        if (lane == 0) invsum[t] = 1.f / sum;
    }

    // ---- Phase D: ct[t,h] = (1/sum) * sum_s p[t,s] * enc[s,h] ----
    int tp = tid >> 5;            // t-pair 0..7
    int h0 = (tid & 31) * 4;      // 4 h per thread
    int tA = tp*2, tB = tA + 1;
    float a0x=0,a0y=0,a0z=0,a0w=0, a1x=0,a1y=0,a1z=0,a1w=0;
    float* encsm = whT;           // reuse (64 x 128, no pad)
    for (int s0 = 0; s0 < SS; s0 += SCHUNK) {
        __syncthreads();          // protect previous chunk reads (also covers softmax writes)
        {
            const float4* ev = (const float4*)(enc + (b*SS + s0)*128);
            float4* esv = (float4*)encsm;
            #pragma unroll
            for (int k = 0; k < 8; k++) esv[tid + 256*k] = ev[tid + 256*k];
        }
        __syncthreads();
        #pragma unroll 4
        for (int ss = 0; ss < SCHUNK; ss++) {
            float4 e = *(const float4*)(encsm + ss*128 + h0);
            float p0 = scores[tA*512 + s0 + ss];   // broadcast
            float p1 = scores[tB*512 + s0 + ss];
            a0x += p0*e.x; a0y += p0*e.y; a0z += p0*e.z; a0w += p0*e.w;
            a1x += p1*e.x; a1y += p1*e.y; a1z += p1*e.z; a1w += p1*e.w;
        }
    }
    float i0 = invsum[tA], i1 = invsum[tB];
    float4 r0 = make_float4(a0x*i0, a0y*i0, a0z*i0, a0w*i0);
    float4 r1 = make_float4(a1x*i1, a1y*i1, a1z*i1, a1w*i1);
    *(float4*)(g_CT + (b*TT + t0 + tA)*128 + h0) = r0;
    *(float4*)(g_CT + (b*TT + t0 + tB)*128 + h0) = r1;
}

// ---------------------------------------------------------------------------
// K3: out[t,o] = tanh( sum_c W[o,c]*concat[t,c] + bias[o] ), c in [0,256)
// grid 256 = (b, t-tile of 16); thread = 4t x 2o (o strided by 64).
// W staged in c-chunks of 128 (pad 129), occ 2.
// ---------------------------------------------------------------------------
__global__ __launch_bounds__(256, 2) void k_out(
    const float* __restrict__ q, const float* __restrict__ Wout,
    const float* __restrict__ bias, float* __restrict__ out)
{
    extern __shared__ float sm[];
    float* concat = sm;               // 16 x 256
    float* Wsm    = concat + 16*256;  // 128 x 129 (c-chunk, pad)
    float* bsm    = Wsm + 128*129;    // 128

    int tid = threadIdx.x;
    int b  = blockIdx.x >> 5;
    int t0 = (blockIdx.x & 31) * 16;

    {   // stage concat (float4)
        #pragma unroll
        for (int k = 0; k < 4; k++) {
            int idx = tid + 256*k;          // 1024 float4
            int t = idx >> 6, c4 = idx & 63;
            float4 v;
            if (c4 < 32) v = *(const float4*)(g_CT + (b*TT + t0 + t)*128 + c4*4);
            else         v = *(const float4*)(q    + (b*TT + t0 + t)*128 + (c4-32)*4);
            *(float4*)(concat + t*256 + c4*4) = v;
        }
    }
    if (tid < 128) bsm[tid] = bias[tid];

    int og = tid & 63;          // o = og, og + 64
    int tg = tid >> 6;          // 4 t-groups x 4 t; warp-uniform
    float acc[4][2];
    #pragma unroll
    for (int k = 0; k < 4; k++) { acc[k][0] = 0.f; acc[k][1] = 0.f; }

    for (int c0 = 0; c0 < 256; c0 += 128) {
        __syncthreads();
        for (int idx = tid; idx < 128*128; idx += 256) {
            int o = idx >> 7, cl = idx & 127;
            Wsm[o*129 + cl] = Wout[o*256 + c0 + cl];
        }
        __syncthreads();
        #pragma unroll 4
        for (int cl = 0; cl < 128; cl++) {
            float w0 = Wsm[og*129 + cl];         // conflict-free (odd stride)
            float w1 = Wsm[(og + 64)*129 + cl];
            int c = c0 + cl;
            #pragma unroll
            for (int k = 0; k < 4; k++) {
                float cc = concat[(tg*4 + k)*256 + c];  // broadcast
                acc[k][0] += w0 * cc;
                acc[k][1] += w1 * cc;
            }
        }
    }
    #pragma unroll
    for (int k = 0; k < 4; k++) {
        int t = t0 + tg*4 + k;
        out[(b*TT + t)*128 + og     ] = tanhf(acc[k][0] + bsm[og]);
        out[(b*TT + t)*128 + og + 64] = tanhf(acc[k][1] + bsm[og + 64]);
    }
}

// ---------------------------------------------------------------------------
extern "C" void kernel_launch(void* const* d_in, const int* in_sizes, int n_in,
                              void* d_out, int out_size)
{
    (void)in_sizes; (void)n_in; (void)out_size;
    const float* q    = (const float*)d_in[0];
    const float* enc  = (const float*)d_in[1];
    const int*   lens = (const int*)  d_in[2];
    const float* Wh   = (const float*)d_in[3];
    const float* Ws   = (const float*)d_in[4];
    const float* v    = (const float*)d_in[5];
    const float* Wout = (const float*)d_in[6];
    const float* bias = (const float*)d_in[7];
    float* out = (float*)d_out;

    int sm1 = (32*128 + 128*36) * 4;                         // 34816 B
    int sm2 = (TTILE*128 + 128*65 + TTILE*512 + 128 + 16)*4; // 74816 B
    int sm3 = (16*256 + 128*129 + 128) * 4;                  // 82944 B
    cudaFuncSetAttribute(k_proj, cudaFuncAttributeMaxDynamicSharedMemorySize, sm1);
    cudaFuncSetAttribute(k_attn, cudaFuncAttributeMaxDynamicSharedMemorySize, sm2);
    cudaFuncSetAttribute(k_out,  cudaFuncAttributeMaxDynamicSharedMemorySize, sm3);

    dim3 g1(128, 2);
    k_proj<<<g1, 256, sm1>>>(q, enc, Ws, Wh);
    k_attn<<<256, 256, sm2>>>(enc, lens, v);
    k_out <<<256, 256, sm3>>>(q, Wout, bias, out);
}

// round 5
// speedup vs baseline: 1.3403x; 1.0844x over previous
#include <cuda_runtime.h>
#include <cuda_fp16.h>
#include <cstdint>

#define BB 8
#define TT 512
#define SS 512
#define HH 128
#define TTILE 16
#define SCHUNK 64

// scratch (allocation-free rule: __device__ globals)
__device__ uint32_t g_WS2[BB*TT/2*HH];   // half2: (WS[t_even], WS[t_odd]) per h
__device__ uint32_t g_WH2[BB*SS*HH];     // half2: (WH, WH) duplicated
__device__ float    g_CT [BB*TT*HH];

__device__ __forceinline__ uint32_t tanh2_u(uint32_t a){
    uint32_t r; asm("tanh.approx.f16x2 %0, %1;" : "=r"(r) : "r"(a)); return r;
}
__device__ __forceinline__ void cp16(uint32_t smem_dst, const void* gsrc){
    asm volatile("cp.async.ca.shared.global [%0], [%1], 16;" :: "r"(smem_dst), "l"(gsrc));
}
#define CP_COMMIT() asm volatile("cp.async.commit_group;")
template<int N> __device__ __forceinline__ void cp_wait(){
    asm volatile("cp.async.wait_group %0;" :: "n"(N));
}

// ---------------------------------------------------------------------------
// K1: projections. grid (128, 2): y=0 -> WS(query,W_s) -> g_WS2 (t-paired h2),
//                                 y=1 -> WH(enc,W_h)   -> g_WH2 (dup h2).
// 32 rows/block; thread = 4 rows x 4 cols; h vectorized by float4.
// ---------------------------------------------------------------------------
__global__ __launch_bounds__(256) void k_proj(
    const float* __restrict__ q, const float* __restrict__ enc,
    const float* __restrict__ Ws, const float* __restrict__ Wh)
{
    extern __shared__ float sm[];
    float* insm = sm;            // 32 x 128
    float* Wsm  = sm + 32*128;   // 128 cols x 36 (stride 36: LDS.128 conflict-free)

    const float* in; const float* W;
    if (blockIdx.y == 0) { in = q;   W = Ws; }
    else                 { in = enc; W = Wh; }
    int tid = threadIdx.x;
    int i0 = blockIdx.x * 32;    // global row (over b*T or b*S)

    {   // stage input rows (float4, coalesced)
        const float4* inv = (const float4*)(in + i0*128);
        float4* insv = (float4*)insm;
        #pragma unroll
        for (int k = 0; k < 4; k++) insv[tid + 256*k] = inv[tid + 256*k];
    }

    int cg = tid & 31;          // cols = cg + 32*j
    int rg = tid >> 5;          // rows = rg*4 + r (warp-uniform)
    float acc[4][4];
    #pragma unroll
    for (int r = 0; r < 4; r++)
        #pragma unroll
        for (int j = 0; j < 4; j++) acc[r][j] = 0.f;

    #pragma unroll 1
    for (int hc = 0; hc < 4; hc++) {          // 32-h chunks
        __syncthreads();
        #pragma unroll
        for (int k = 0; k < 4; k++) {         // stage W chunk: 128 cols x 32 h = 1024 float4
            int idx = tid + 256*k;
            int col = idx >> 3, kk = idx & 7;
            float4 w = *(const float4*)(W + col*128 + hc*32 + kk*4);
            *(float4*)(Wsm + col*36 + kk*4) = w;
        }
        __syncthreads();
        #pragma unroll
        for (int k8 = 0; k8 < 8; k8++) {
            float4 cv[4];
            #pragma unroll
            for (int j = 0; j < 4; j++)
                cv[j] = *(const float4*)(Wsm + (cg + 32*j)*36 + k8*4);
            float4 rv[4];
            #pragma unroll
            for (int r = 0; r < 4; r++)
                rv[r] = *(const float4*)(insm + (rg*4 + r)*128 + hc*32 + k8*4);
            #pragma unroll
            for (int r = 0; r < 4; r++)
                #pragma unroll
                for (int j = 0; j < 4; j++) {
                    acc[r][j] += rv[r].x*cv[j].x;
                    acc[r][j] += rv[r].y*cv[j].y;
                    acc[r][j] += rv[r].z*cv[j].z;
                    acc[r][j] += rv[r].w*cv[j].w;
                }
        }
    }
    if (blockIdx.y == 0) {
        // pack t-pairs: rows (rg*4+0, +1) and (+2, +3)
        #pragma unroll
        for (int r = 0; r < 4; r += 2)
            #pragma unroll
            for (int j = 0; j < 4; j++) {
                __half2 p = __floats2half2_rn(acc[r][j], acc[r+1][j]);  // x=even t
                int pair = (i0 + rg*4 + r) >> 1;
                g_WS2[pair*128 + cg + 32*j] = *(uint32_t*)&p;
            }
    } else {
        #pragma unroll
        for (int r = 0; r < 4; r++)
            #pragma unroll
            for (int j = 0; j < 4; j++) {
                __half2 d = __half2half2(__float2half_rn(acc[r][j]));
                g_WH2[(i0 + rg*4 + r)*128 + cg + 32*j] = *(uint32_t*)&d;
            }
    }
}

// ---------------------------------------------------------------------------
// K2: fused scores (f16x2 tanh) + masked softmax + ct.
// grid 256 = (b, t-tile of 16), 256 threads, occ 2.
// ---------------------------------------------------------------------------
#define NB_U32   (SCHUNK*132)                 // one staging buffer, u32 units
#define OFF_BUF0 0
#define OFF_BUF1 (NB_U32)
#define OFF_SC   (2*NB_U32)                   // scores: 16*512 floats
#define OFF_WS2  (OFF_SC + TTILE*512)         // 8 t-pairs x 128 h (u32)
#define OFF_V    (OFF_WS2 + 8*128)            // 128 floats
#define OFF_INV  (OFF_V + 128)                // 16 floats
#define SM2_U32  (OFF_INV + 16)

__global__ __launch_bounds__(256, 2) void k_attn(
    const float* __restrict__ enc, const int* __restrict__ lens,
    const float* __restrict__ vvec)
{
    extern __shared__ uint32_t smu[];
    float*    scores = (float*)(smu + OFF_SC);
    uint32_t* wsh2   = smu + OFF_WS2;
    float*    vsm    = (float*)(smu + OFF_V);
    float*    invsum = (float*)(smu + OFF_INV);
    uint32_t  smbase = (uint32_t)__cvta_generic_to_shared(smu);

    int tid = threadIdx.x;
    int b  = blockIdx.x >> 5;
    int t0 = (blockIdx.x & 31) * TTILE;
    int len = __ldg(&lens[b]);
    int warp = tid >> 5, lane = tid & 31;

    // prefetch WH2 chunk 0 into buf0 (16B cp.async, s-major rows w/ pad 132)
    {
        const uint32_t* src0 = g_WH2 + (b*SS)*128;
        #pragma unroll
        for (int k = 0; k < 8; k++) {
            int idx = tid + 256*k;            // 2048 x 16B
            int ss = idx >> 5, kk = idx & 31;
            cp16(smbase + (OFF_BUF0 + ss*132 + kk*4)*4, src0 + ss*128 + kk*4);
        }
        CP_COMMIT();
    }

    // stage ws pairs + v
    {
        const uint32_t* wsrc = g_WS2 + (b*256 + t0/2)*128;
        #pragma unroll
        for (int k = 0; k < 4; k++) wsh2[tid + 256*k] = wsrc[tid + 256*k];
        if (tid < 128) vsm[tid] = vvec[tid];
    }

    // ---- Phase B: scores. warp = (t-quad tq, s-half sh). f16x2 MUFU tanh. ----
    int tq = warp >> 1, sh = warp & 1;
    int s  = sh*32 + lane;
    const uint32_t* wsA = wsh2 + (tq*2 + 0)*128;   // (t=4tq+0, 4tq+1)
    const uint32_t* wsB = wsh2 + (tq*2 + 1)*128;   // (t=4tq+2, 4tq+3)

    for (int c = 0; c < 8; c++) {
        // prefetch next chunk (or enc chunk 0 for phase D on the last iter)
        if (c + 1 < 8) {
            const uint32_t* src = g_WH2 + (b*SS + (c+1)*SCHUNK)*128;
            uint32_t dstoff = ((c+1) & 1) ? OFF_BUF1 : OFF_BUF0;
            #pragma unroll
            for (int k = 0; k < 8; k++) {
                int idx = tid + 256*k;
                int ss = idx >> 5, kk = idx & 31;
                cp16(smbase + (dstoff + ss*132 + kk*4)*4, src + ss*128 + kk*4);
            }
        } else {
            const float* src = enc + (b*SS)*128;
            #pragma unroll
            for (int k = 0; k < 8; k++) {
                int idx = tid + 256*k;
                int ss = idx >> 5, kk = idx & 31;
                cp16(smbase + (OFF_BUF0 + ss*128 + kk*4)*4, src + ss*128 + kk*4);
            }
        }
        CP_COMMIT();
        cp_wait<1>();
        __syncthreads();

        const uint32_t* whrow = smu + ((c & 1) ? OFF_BUF1 : OFF_BUF0) + s*132;
        float a0 = 0.f, a1 = 0.f, a2 = 0.f, a3 = 0.f;
        #pragma unroll 8
        for (int hb = 0; hb < 128; hb += 4) {
            uint4 wh4 = *(const uint4*)(whrow + hb);
            uint4 wA4 = *(const uint4*)(wsA + hb);
            uint4 wB4 = *(const uint4*)(wsB + hb);
            float4 v4 = *(const float4*)(vsm + hb);
            #define STEP(WH, WA, WB, VV)                                         \
            {                                                                    \
                __half2 hw = *(__half2*)&(WH);                                   \
                __half2 aA = __hadd2(hw, *(__half2*)&(WA));                      \
                __half2 aB = __hadd2(hw, *(__half2*)&(WB));                      \
                uint32_t tA = tanh2_u(*(uint32_t*)&aA);                          \
                uint32_t tB = tanh2_u(*(uint32_t*)&aB);                          \
                float2 fA = __half22float2(*(__half2*)&tA);                      \
                float2 fB = __half22float2(*(__half2*)&tB);                      \
                a0 += (VV)*fA.x; a1 += (VV)*fA.y;                                \
                a2 += (VV)*fB.x; a3 += (VV)*fB.y;                                \
            }
            STEP(wh4.x, wA4.x, wB4.x, v4.x)
            STEP(wh4.y, wA4.y, wB4.y, v4.y)
            STEP(wh4.z, wA4.z, wB4.z, v4.z)
            STEP(wh4.w, wA4.w, wB4.w, v4.w)
            #undef STEP
        }
        int sg = c*SCHUNK + s;
        float m = (sg < len) ? 1.f : 0.f;     // reference quirk: zero, not -inf
        scores[(tq*4 + 0)*512 + sg] = a0 * m;
        scores[(tq*4 + 1)*512 + sg] = a1 * m;
        scores[(tq*4 + 2)*512 + sg] = a2 * m;
        scores[(tq*4 + 3)*512 + sg] = a3 * m;
        __syncthreads();
    }

    // ---- Phase C: softmax over full 512 (zeros included) ----
    #pragma unroll
    for (int it = 0; it < 2; it++) {
        int t = warp + 8*it;
        float* row = scores + t*512;
        float loc[16];
        float mx = -1e30f;
        #pragma unroll
        for (int k = 0; k < 16; k++) { loc[k] = row[lane + 32*k]; mx = fmaxf(mx, loc[k]); }
        #pragma unroll
        for (int o = 16; o > 0; o >>= 1) mx = fmaxf(mx, __shfl_xor_sync(0xffffffffu, mx, o));
        float sum = 0.f;
        #pragma unroll
        for (int k = 0; k < 16; k++) {
            float p = __expf(loc[k] - mx);
            row[lane + 32*k] = p;
            sum += p;
        }
        #pragma unroll
        for (int o = 16; o > 0; o >>= 1) sum += __shfl_xor_sync(0xffffffffu, sum, o);
        if (lane == 0) invsum[t] = 1.f / sum;
    }

    // ---- Phase D: ct[t,h] = (1/sum) * sum_s p[t,s] * enc[s,h] ----
    int tp = tid >> 5;            // t-pair 0..7
    int h0 = (tid & 31) * 4;      // 4 h per thread
    int tA = tp*2, tB = tA + 1;
    float a0x=0,a0y=0,a0z=0,a0w=0, a1x=0,a1y=0,a1z=0,a1w=0;
    for (int d = 0; d < 8; d++) {
        if (d + 1 < 8) {
            const float* src = enc + (b*SS + (d+1)*SCHUNK)*128;
            uint32_t dstoff = ((d+1) & 1) ? OFF_BUF1 : OFF_BUF0;
            #pragma unroll
            for (int k = 0; k < 8; k++) {
                int idx = tid + 256*k;
                int ss = idx >> 5, kk = idx & 31;
                cp16(smbase + (dstoff + ss*128 + kk*4)*4, src + ss*128 + kk*4);
            }
            CP_COMMIT();
            cp_wait<1>();
        } else {
            cp_wait<0>();
        }
        __syncthreads();
        const float* encsm = (const float*)(smu + ((d & 1) ? OFF_BUF1 : OFF_BUF0));
        #pragma unroll 4
        for (int ss = 0; ss < SCHUNK; ss++) {
            float4 e = *(const float4*)(encsm + ss*128 + h0);
            float p0 = scores[tA*512 + d*SCHUNK + ss];   // broadcast
            float p1 = scores[tB*512 + d*SCHUNK + ss];
            a0x += p0*e.x; a0y += p0*e.y; a0z += p0*e.z; a0w += p0*e.w;
            a1x += p1*e.x; a1y += p1*e.y; a1z += p1*e.z; a1w += p1*e.w;
        }
        __syncthreads();
    }
    float i0 = invsum[tA], i1 = invsum[tB];
    float4 r0 = make_float4(a0x*i0, a0y*i0, a0z*i0, a0w*i0);
    float4 r1 = make_float4(a1x*i1, a1y*i1, a1z*i1, a1w*i1);
    *(float4*)(g_CT + (b*TT + t0 + tA)*128 + h0) = r0;
    *(float4*)(g_CT + (b*TT + t0 + tB)*128 + h0) = r1;
}

// ---------------------------------------------------------------------------
// K3: out[t,o] = tanh( sum_c W[o,c]*concat[t,c] + bias[o] )
// grid 256 = (b, t-tile of 16); thread = 4t x 2o; c vectorized by float4.
// ---------------------------------------------------------------------------
__global__ __launch_bounds__(256, 2) void k_out(
    const float* __restrict__ q, const float* __restrict__ Wout,
    const float* __restrict__ bias, float* __restrict__ out)
{
    extern __shared__ float sm[];
    float* concat = sm;               // 16 x 256
    float* Wsm    = concat + 16*256;  // 128 x 132 (c-chunk, LDS.128-friendly pad)
    float* bsm    = Wsm + 128*132;    // 128

    int tid = threadIdx.x;
    int b  = blockIdx.x >> 5;
    int t0 = (blockIdx.x & 31) * 16;

    {   // stage concat (float4)
        #pragma unroll
        for (int k = 0; k < 4; k++) {
            int idx = tid + 256*k;          // 1024 float4
            int t = idx >> 6, c4 = idx & 63;
            float4 v;
            if (c4 < 32) v = *(const float4*)(g_CT + (b*TT + t0 + t)*128 + c4*4);
            else         v = *(const float4*)(q    + (b*TT + t0 + t)*128 + (c4-32)*4);
            *(float4*)(concat + t*256 + c4*4) = v;
        }
    }
    if (tid < 128) bsm[tid] = bias[tid];

    int og = tid & 63;          // o = og, og + 64
    int tg = tid >> 6;          // 4 t-groups x 4 t; warp-uniform
    float acc[4][2];
    #pragma unroll
    for (int k = 0; k < 4; k++) { acc[k][0] = 0.f; acc[k][1] = 0.f; }

    for (int c0 = 0; c0 < 256; c0 += 128) {
        __syncthreads();
        // FIXED staging: chunk is 128 o x 128 c = 4096 float4 (16 iters x 256 thr)
        #pragma unroll
        for (int k = 0; k < 16; k++) {
            int idx = tid + 256*k;
            int o = idx >> 5, kk = idx & 31;      // kk*4 covers c 0..127
            float4 w = *(const float4*)(Wout + o*256 + c0 + kk*4);
            *(float4*)(Wsm + o*132 + kk*4) = w;
        }
        __syncthreads();
        #pragma unroll 4
        for (int cl = 0; cl < 128; cl += 4) {
            float4 w0 = *(const float4*)(Wsm + og*132 + cl);
            float4 w1 = *(const float4*)(Wsm + (og + 64)*132 + cl);
            #pragma unroll
            for (int k = 0; k < 4; k++) {
                float4 cc = *(const float4*)(concat + (tg*4 + k)*256 + c0 + cl);
                acc[k][0] += w0.x*cc.x + w0.y*cc.y + w0.z*cc.z + w0.w*cc.w;
                acc[k][1] += w1.x*cc.x + w1.y*cc.y + w1.z*cc.z + w1.w*cc.w;
            }
        }
    }
    #pragma unroll
    for (int k = 0; k < 4; k++) {
        int t = t0 + tg*4 + k;
        out[(b*TT + t)*128 + og     ] = tanhf(acc[k][0] + bsm[og]);
        out[(b*TT + t)*128 + og + 64] = tanhf(acc[k][1] + bsm[og + 64]);
    }
}

// ---------------------------------------------------------------------------
extern "C" void kernel_launch(void* const* d_in, const int* in_sizes, int n_in,
                              void* d_out, int out_size)
{
    (void)in_sizes; (void)n_in; (void)out_size;
    const float* q    = (const float*)d_in[0];
    const float* enc  = (const float*)d_in[1];
    const int*   lens = (const int*)  d_in[2];
    const float* Wh   = (const float*)d_in[3];
    const float* Ws   = (const float*)d_in[4];
    const float* v    = (const float*)d_in[5];
    const float* Wout = (const float*)d_in[6];
    const float* bias = (const float*)d_in[7];
    float* out = (float*)d_out;

    int sm1 = (32*128 + 128*36) * 4;     // 34816 B
    int sm2 = SM2_U32 * 4;               // ~105 KB
    int sm3 = (16*256 + 128*132 + 128) * 4;
    cudaFuncSetAttribute(k_proj, cudaFuncAttributeMaxDynamicSharedMemorySize, sm1);
    cudaFuncSetAttribute(k_attn, cudaFuncAttributeMaxDynamicSharedMemorySize, sm2);
    cudaFuncSetAttribute(k_out,  cudaFuncAttributeMaxDynamicSharedMemorySize, sm3);

    dim3 g1(128, 2);
    k_proj<<<g1, 256, sm1>>>(q, enc, Ws, Wh);
    k_attn<<<256, 256, sm2>>>(enc, lens, v);
    k_out <<<256, 256, sm3>>>(q, Wout, bias, out);
}

// round 6
// speedup vs baseline: 1.3495x; 1.0069x over previous
#include <cuda_runtime.h>
#include <cuda_fp16.h>
#include <cstdint>

#define BB 8
#define TT 512
#define SS 512
#define HH 128
#define TTILE 16
#define SCHUNK 64

// scratch (allocation-free rule: __device__ globals)
__device__ uint32_t g_WS2[BB*TT/2*HH];   // half2: (WS[t_even], WS[t_odd]) per h
__device__ uint32_t g_WH2[BB*SS*HH];     // half2: (WH, WH) duplicated
__device__ float    g_CT [BB*TT*HH];

__device__ __forceinline__ uint32_t tanh2_u(uint32_t a){
    uint32_t r; asm("tanh.approx.f16x2 %0, %1;" : "=r"(r) : "r"(a)); return r;
}
__device__ __forceinline__ void cp16(uint32_t smem_dst, const void* gsrc){
    asm volatile("cp.async.ca.shared.global [%0], [%1], 16;" :: "r"(smem_dst), "l"(gsrc));
}
#define CP_COMMIT() asm volatile("cp.async.commit_group;")
template<int N> __device__ __forceinline__ void cp_wait(){
    asm volatile("cp.async.wait_group %0;" :: "n"(N));
}

// ---------------------------------------------------------------------------
// K1: projections. grid (128, 2): y=0 -> WS(query,W_s) -> g_WS2 (t-paired h2),
//                                 y=1 -> WH(enc,W_h)   -> g_WH2 (dup h2).
// 32 rows/block; thread = 4 rows x 4 cols; h vectorized by float4.
// ---------------------------------------------------------------------------
__global__ __launch_bounds__(256) void k_proj(
    const float* __restrict__ q, const float* __restrict__ enc,
    const float* __restrict__ Ws, const float* __restrict__ Wh)
{
    extern __shared__ float sm[];
    float* insm = sm;            // 32 x 128
    float* Wsm  = sm + 32*128;   // 128 cols x 36 (stride 36: LDS.128 conflict-free)

    const float* in; const float* W;
    if (blockIdx.y == 0) { in = q;   W = Ws; }
    else                 { in = enc; W = Wh; }
    int tid = threadIdx.x;
    int i0 = blockIdx.x * 32;    // global row (over b*T or b*S)

    {   // stage input rows (float4, coalesced)
        const float4* inv = (const float4*)(in + i0*128);
        float4* insv = (float4*)insm;
        #pragma unroll
        for (int k = 0; k < 4; k++) insv[tid + 256*k] = inv[tid + 256*k];
    }

    int cg = tid & 31;          // cols = cg + 32*j
    int rg = tid >> 5;          // rows = rg*4 + r (warp-uniform)
    float acc[4][4];
    #pragma unroll
    for (int r = 0; r < 4; r++)
        #pragma unroll
        for (int j = 0; j < 4; j++) acc[r][j] = 0.f;

    #pragma unroll 1
    for (int hc = 0; hc < 4; hc++) {          // 32-h chunks
        __syncthreads();
        #pragma unroll
        for (int k = 0; k < 4; k++) {         // stage W chunk: 128 cols x 32 h = 1024 float4
            int idx = tid + 256*k;
            int col = idx >> 3, kk = idx & 7;
            float4 w = *(const float4*)(W + col*128 + hc*32 + kk*4);
            *(float4*)(Wsm + col*36 + kk*4) = w;
        }
        __syncthreads();
        #pragma unroll
        for (int k8 = 0; k8 < 8; k8++) {
            float4 cv[4];
            #pragma unroll
            for (int j = 0; j < 4; j++)
                cv[j] = *(const float4*)(Wsm + (cg + 32*j)*36 + k8*4);
            float4 rv[4];
            #pragma unroll
            for (int r = 0; r < 4; r++)
                rv[r] = *(const float4*)(insm + (rg*4 + r)*128 + hc*32 + k8*4);
            #pragma unroll
            for (int r = 0; r < 4; r++)
                #pragma unroll
                for (int j = 0; j < 4; j++) {
                    acc[r][j] += rv[r].x*cv[j].x;
                    acc[r][j] += rv[r].y*cv[j].y;
                    acc[r][j] += rv[r].z*cv[j].z;
                    acc[r][j] += rv[r].w*cv[j].w;
                }
        }
    }
    if (blockIdx.y == 0) {
        // pack t-pairs: rows (rg*4+0, +1) and (+2, +3)
        #pragma unroll
        for (int r = 0; r < 4; r += 2)
            #pragma unroll
            for (int j = 0; j < 4; j++) {
                __half2 p = __floats2half2_rn(acc[r][j], acc[r+1][j]);  // x=even t
                int pair = (i0 + rg*4 + r) >> 1;
                g_WS2[pair*128 + cg + 32*j] = *(uint32_t*)&p;
            }
    } else {
        #pragma unroll
        for (int r = 0; r < 4; r++)
            #pragma unroll
            for (int j = 0; j < 4; j++) {
                __half2 d = __half2half2(__float2half_rn(acc[r][j]));
                g_WH2[(i0 + rg*4 + r)*128 + cg + 32*j] = *(uint32_t*)&d;
            }
    }
}

// ---------------------------------------------------------------------------
// K2: fused scores (f16x2 tanh, hfma2 accumulation) + masked softmax + ct.
// grid 256 = (b, t-tile of 16), 256 threads, occ 2.
// ---------------------------------------------------------------------------
#define NB_U32   (SCHUNK*132)                 // one staging buffer, u32 units
#define OFF_BUF0 0
#define OFF_BUF1 (NB_U32)
#define OFF_SC   (2*NB_U32)                   // scores: 16*512 floats
#define OFF_WS2  (OFF_SC + TTILE*512)         // 8 t-pairs x 128 h (u32)
#define OFF_V    (OFF_WS2 + 8*128)            // 128 u32 (dup half2 of v)
#define OFF_INV  (OFF_V + 128)                // 16 floats
#define SM2_U32  (OFF_INV + 16)

__global__ __launch_bounds__(256, 2) void k_attn(
    const float* __restrict__ enc, const int* __restrict__ lens,
    const float* __restrict__ vvec)
{
    extern __shared__ uint32_t smu[];
    float*    scores = (float*)(smu + OFF_SC);
    uint32_t* wsh2   = smu + OFF_WS2;
    uint32_t* vsm2   = smu + OFF_V;
    float*    invsum = (float*)(smu + OFF_INV);
    uint32_t  smbase = (uint32_t)__cvta_generic_to_shared(smu);

    int tid = threadIdx.x;
    int b  = blockIdx.x >> 5;
    int t0 = (blockIdx.x & 31) * TTILE;
    int len = __ldg(&lens[b]);
    int warp = tid >> 5, lane = tid & 31;

    // prefetch WH2 chunk 0 into buf0 (16B cp.async, s-major rows w/ pad 132)
    {
        const uint32_t* src0 = g_WH2 + (b*SS)*128;
        #pragma unroll
        for (int k = 0; k < 8; k++) {
            int idx = tid + 256*k;            // 2048 x 16B
            int ss = idx >> 5, kk = idx & 31;
            cp16(smbase + (OFF_BUF0 + ss*132 + kk*4)*4, src0 + ss*128 + kk*4);
        }
        CP_COMMIT();
    }

    // stage ws pairs + v (dup half2)
    {
        const uint32_t* wsrc = g_WS2 + (b*256 + t0/2)*128;
        #pragma unroll
        for (int k = 0; k < 4; k++) wsh2[tid + 256*k] = wsrc[tid + 256*k];
        if (tid < 128) {
            __half2 d = __half2half2(__float2half_rn(vvec[tid]));
            vsm2[tid] = *(uint32_t*)&d;
        }
    }

    // ---- Phase B: scores. warp = (t-quad tq, s-half sh). f16x2 tanh + hfma2. ----
    int tq = warp >> 1, sh = warp & 1;
    int s  = sh*32 + lane;
    const uint32_t* wsA = wsh2 + (tq*2 + 0)*128;   // (t=4tq+0, 4tq+1)
    const uint32_t* wsB = wsh2 + (tq*2 + 1)*128;   // (t=4tq+2, 4tq+3)

    for (int c = 0; c < 8; c++) {
        // prefetch next chunk (or enc chunk 0 for phase D on the last iter)
        if (c + 1 < 8) {
            const uint32_t* src = g_WH2 + (b*SS + (c+1)*SCHUNK)*128;
            uint32_t dstoff = ((c+1) & 1) ? OFF_BUF1 : OFF_BUF0;
            #pragma unroll
            for (int k = 0; k < 8; k++) {
                int idx = tid + 256*k;
                int ss = idx >> 5, kk = idx & 31;
                cp16(smbase + (dstoff + ss*132 + kk*4)*4, src + ss*128 + kk*4);
            }
        } else {
            const float* src = enc + (b*SS)*128;
            #pragma unroll
            for (int k = 0; k < 8; k++) {
                int idx = tid + 256*k;
                int ss = idx >> 5, kk = idx & 31;
                cp16(smbase + (OFF_BUF0 + ss*128 + kk*4)*4, src + ss*128 + kk*4);
            }
        }
        CP_COMMIT();
        cp_wait<1>();
        __syncthreads();

        const uint32_t* whrow = smu + ((c & 1) ? OFF_BUF1 : OFF_BUF0) + s*132;
        float a0 = 0.f, a1 = 0.f, a2 = 0.f, a3 = 0.f;
        #pragma unroll
        for (int hb = 0; hb < 128; hb += 8) {      // flush f16 accumulators every 8 h
            __half2 accA = __float2half2_rn(0.f);
            __half2 accB = __float2half2_rn(0.f);
            #pragma unroll
            for (int g = 0; g < 8; g += 4) {
                uint4 wh4 = *(const uint4*)(whrow + hb + g);
                uint4 wA4 = *(const uint4*)(wsA + hb + g);
                uint4 wB4 = *(const uint4*)(wsB + hb + g);
                uint4 vv4 = *(const uint4*)(vsm2 + hb + g);
                #define STEP(WH, WA, WB, VV)                                     \
                {                                                                \
                    __half2 hw = *(__half2*)&(WH);                               \
                    __half2 aA = __hadd2(hw, *(__half2*)&(WA));                  \
                    __half2 aB = __hadd2(hw, *(__half2*)&(WB));                  \
                    uint32_t tA = tanh2_u(*(uint32_t*)&aA);                      \
                    uint32_t tB = tanh2_u(*(uint32_t*)&aB);                      \
                    __half2 v2 = *(__half2*)&(VV);                               \
                    accA = __hfma2(v2, *(__half2*)&tA, accA);                    \
                    accB = __hfma2(v2, *(__half2*)&tB, accB);                    \
                }
                STEP(wh4.x, wA4.x, wB4.x, vv4.x)
                STEP(wh4.y, wA4.y, wB4.y, vv4.y)
                STEP(wh4.z, wA4.z, wB4.z, vv4.z)
                STEP(wh4.w, wA4.w, wB4.w, vv4.w)
                #undef STEP
            }
            float2 fA = __half22float2(accA);
            float2 fB = __half22float2(accB);
            a0 += fA.x; a1 += fA.y;
            a2 += fB.x; a3 += fB.y;
        }
        int sg = c*SCHUNK + s;
        float m = (sg < len) ? 1.f : 0.f;     // reference quirk: zero, not -inf
        scores[(tq*4 + 0)*512 + sg] = a0 * m;
        scores[(tq*4 + 1)*512 + sg] = a1 * m;
        scores[(tq*4 + 2)*512 + sg] = a2 * m;
        scores[(tq*4 + 3)*512 + sg] = a3 * m;
        __syncthreads();
    }

    // ---- Phase C: softmax over full 512 (zeros included) ----
    #pragma unroll
    for (int it = 0; it < 2; it++) {
        int t = warp + 8*it;
        float* row = scores + t*512;
        float loc[16];
        float mx = -1e30f;
        #pragma unroll
        for (int k = 0; k < 16; k++) { loc[k] = row[lane + 32*k]; mx = fmaxf(mx, loc[k]); }
        #pragma unroll
        for (int o = 16; o > 0; o >>= 1) mx = fmaxf(mx, __shfl_xor_sync(0xffffffffu, mx, o));
        float sum = 0.f;
        #pragma unroll
        for (int k = 0; k < 16; k++) {
            float p = __expf(loc[k] - mx);
            row[lane + 32*k] = p;
            sum += p;
        }
        #pragma unroll
        for (int o = 16; o > 0; o >>= 1) sum += __shfl_xor_sync(0xffffffffu, sum, o);
        if (lane == 0) invsum[t] = 1.f / sum;
    }

    // ---- Phase D: ct[t,h] = (1/sum) * sum_s p[t,s] * enc[s,h] ----
    int tp = tid >> 5;            // t-pair 0..7
    int h0 = (tid & 31) * 4;      // 4 h per thread
    int tA = tp*2, tB = tA + 1;
    float a0x=0,a0y=0,a0z=0,a0w=0, a1x=0,a1y=0,a1z=0,a1w=0;
    for (int d = 0; d < 8; d++) {
        if (d + 1 < 8) {
            const float* src = enc + (b*SS + (d+1)*SCHUNK)*128;
            uint32_t dstoff = ((d+1) & 1) ? OFF_BUF1 : OFF_BUF0;
            #pragma unroll
            for (int k = 0; k < 8; k++) {
                int idx = tid + 256*k;
                int ss = idx >> 5, kk = idx & 31;
                cp16(smbase + (dstoff + ss*128 + kk*4)*4, src + ss*128 + kk*4);
            }
            CP_COMMIT();
            cp_wait<1>();
        } else {
            cp_wait<0>();
        }
        __syncthreads();
        const float* encsm = (const float*)(smu + ((d & 1) ? OFF_BUF1 : OFF_BUF0));
        #pragma unroll 4
        for (int ss = 0; ss < SCHUNK; ss++) {
            float4 e = *(const float4*)(encsm + ss*128 + h0);
            float p0 = scores[tA*512 + d*SCHUNK + ss];   // broadcast
            float p1 = scores[tB*512 + d*SCHUNK + ss];
            a0x += p0*e.x; a0y += p0*e.y; a0z += p0*e.z; a0w += p0*e.w;
            a1x += p1*e.x; a1y += p1*e.y; a1z += p1*e.z; a1w += p1*e.w;
        }
        __syncthreads();
    }
    float i0 = invsum[tA], i1 = invsum[tB];
    float4 r0 = make_float4(a0x*i0, a0y*i0, a0z*i0, a0w*i0);
    float4 r1 = make_float4(a1x*i1, a1y*i1, a1z*i1, a1w*i1);
    *(float4*)(g_CT + (b*TT + t0 + tA)*128 + h0) = r0;
    *(float4*)(g_CT + (b*TT + t0 + tB)*128 + h0) = r1;
}

// ---------------------------------------------------------------------------
// K3: out[t,o] = tanh( sum_c W[o,c]*concat[t,c] + bias[o] )
// grid 256 = (b, t-tile of 16); thread = 4t x 2o; c vectorized by float4.
// ---------------------------------------------------------------------------
__global__ __launch_bounds__(256, 2) void k_out(
    const float* __restrict__ q, const float* __restrict__ Wout,
    const float* __restrict__ bias, float* __restrict__ out)
{
    extern __shared__ float sm[];
    float* concat = sm;               // 16 x 256
    float* Wsm    = concat + 16*256;  // 128 x 132 (c-chunk, LDS.128-friendly pad)
    float* bsm    = Wsm + 128*132;    // 128

    int tid = threadIdx.x;
    int b  = blockIdx.x >> 5;
    int t0 = (blockIdx.x & 31) * 16;

    {   // stage concat (float4)
        #pragma unroll
        for (int k = 0; k < 4; k++) {
            int idx = tid + 256*k;          // 1024 float4
            int t = idx >> 6, c4 = idx & 63;
            float4 v;
            if (c4 < 32) v = *(const float4*)(g_CT + (b*TT + t0 + t)*128 + c4*4);
            else         v = *(const float4*)(q    + (b*TT + t0 + t)*128 + (c4-32)*4);
            *(float4*)(concat + t*256 + c4*4) = v;
        }
    }
    if (tid < 128) bsm[tid] = bias[tid];

    int og = tid & 63;          // o = og, og + 64
    int tg = tid >> 6;          // 4 t-groups x 4 t; warp-uniform
    float acc[4][2];
    #pragma unroll
    for (int k = 0; k < 4; k++) { acc[k][0] = 0.f; acc[k][1] = 0.f; }

    for (int c0 = 0; c0 < 256; c0 += 128) {
        __syncthreads();
        // staging: chunk is 128 o x 128 c = 4096 float4 (16 iters x 256 thr)
        #pragma unroll
        for (int k = 0; k < 16; k++) {
            int idx = tid + 256*k;
            int o = idx >> 5, kk = idx & 31;      // kk*4 covers c 0..127
            float4 w = *(const float4*)(Wout + o*256 + c0 + kk*4);
            *(float4*)(Wsm + o*132 + kk*4) = w;
        }
        __syncthreads();
        #pragma unroll 4
        for (int cl = 0; cl < 128; cl += 4) {
            float4 w0 = *(const float4*)(Wsm + og*132 + cl);
            float4 w1 = *(const float4*)(Wsm + (og + 64)*132 + cl);
            #pragma unroll
            for (int k = 0; k < 4; k++) {
                float4 cc = *(const float4*)(concat + (tg*4 + k)*256 + c0 + cl);
                acc[k][0] += w0.x*cc.x + w0.y*cc.y + w0.z*cc.z + w0.w*cc.w;
                acc[k][1] += w1.x*cc.x + w1.y*cc.y + w1.z*cc.z + w1.w*cc.w;
            }
        }
    }
    #pragma unroll
    for (int k = 0; k < 4; k++) {
        int t = t0 + tg*4 + k;
        out[(b*TT + t)*128 + og     ] = tanhf(acc[k][0] + bsm[og]);
        out[(b*TT + t)*128 + og + 64] = tanhf(acc[k][1] + bsm[og + 64]);
    }
}

// ---------------------------------------------------------------------------
extern "C" void kernel_launch(void* const* d_in, const int* in_sizes, int n_in,
                              void* d_out, int out_size)
{
    (void)in_sizes; (void)n_in; (void)out_size;
    const float* q    = (const float*)d_in[0];
    const float* enc  = (const float*)d_in[1];
    const int*   lens = (const int*)  d_in[2];
    const float* Wh   = (const float*)d_in[3];
    const float* Ws   = (const float*)d_in[4];
    const float* v    = (const float*)d_in[5];
    const float* Wout = (const float*)d_in[6];
    const float* bias = (const float*)d_in[7];
    float* out = (float*)d_out;

    int sm1 = (32*128 + 128*36) * 4;     // 34816 B
    int sm2 = SM2_U32 * 4;               // ~105 KB
    int sm3 = (16*256 + 128*132 + 128) * 4;
    cudaFuncSetAttribute(k_proj, cudaFuncAttributeMaxDynamicSharedMemorySize, sm1);
    cudaFuncSetAttribute(k_attn, cudaFuncAttributeMaxDynamicSharedMemorySize, sm2);
    cudaFuncSetAttribute(k_out,  cudaFuncAttributeMaxDynamicSharedMemorySize, sm3);

    dim3 g1(128, 2);
    k_proj<<<g1, 256, sm1>>>(q, enc, Ws, Wh);
    k_attn<<<256, 256, sm2>>>(enc, lens, v);
    k_out <<<256, 256, sm3>>>(q, Wout, bias, out);
}